// round 11
// baseline (speedup 1.0000x reference)
#include <cuda_runtime.h>
#include <cuda_bf16.h>
#include <math_constants.h>
#include <cstdint>

#define B_PAT 4096
#define N_DIS 10000
#define DIM   256
#define BM    128                 // patients per CTA (GEMM M)
#define KC    64                  // nodes per chunk (GEMM K chunk)
#define NSK   4                   // K splits
#define NPER  (N_DIS/NSK)         // 2500 valid nodes per split
#define NCH   ((NPER+KC-1)/KC)    // 40 chunks per split
#define NPADS (NCH*KC)            // 2560 padded columns per split
#define NPAD  (NSK*NPADS)         // 10240
#define PT    (B_PAT/BM)          // 32
#define NTHR  512                 // 16 warps
#define LEAKY 0.2f
#define L2EF  1.4426950408889634f

// dynamic smem layout
#define A_BYTES  (BM*KC*2)                // 16384 per buffer
#define B_BYTES  (DIM*KC*2)               // 32768 per buffer
#define OFF_A    0
#define OFF_B    (2*A_BYTES)              // 32768
#define OFF_SN   (OFF_B + 2*B_BYTES)      // 98304
#define OFF_DEN  (OFF_SN + NPER*4)        // 108304
#define SMEM_TOTAL (OFF_DEN + NTHR*4)     // 110352

typedef uint32_t u32;

// ---------------- device globals (no allocation) ----------------
__device__ float        g_sp[B_PAT];
__device__ float        g_sn[N_DIS];
__device__ unsigned int g_max_enc;
// padded split-major transpose: split s owns padded cols [s*NPADS, (s+1)*NPADS)
__device__ __align__(16) __nv_bfloat16 g_dnT[DIM][NPAD];
__device__ float        g_num[NSK][B_PAT][DIM];
__device__ float        g_den[NSK][B_PAT];
__device__ float        g_invden[B_PAT];

// ---------------- helpers ----------------
__device__ __forceinline__ unsigned enc_f(float f) {
    unsigned u = __float_as_uint(f);
    return (u & 0x80000000u) ? ~u : (u | 0x80000000u);
}
__device__ __forceinline__ float dec_f(unsigned e) {
    return __uint_as_float((e & 0x80000000u) ? (e ^ 0x80000000u) : ~e);
}
__device__ __forceinline__ float ex2(float x) {
    float r; asm("ex2.approx.ftz.f32 %0, %1;" : "=f"(r) : "f"(x)); return r;
}
__device__ __forceinline__ u32 smem_u32(const void* p) {
    u32 a;
    asm("{ .reg .u64 t; cvta.to.shared.u64 t, %1; cvt.u32.u64 %0, t; }" : "=r"(a) : "l"(p));
    return a;
}
// swizzled byte offset, k multiple of 8 (one 16B unit)
__device__ __forceinline__ u32 swz8(int r, int k) {
    return (u32)(r * 128 + ((((k >> 3) & 7) ^ (r & 7)) << 4));
}
__device__ __forceinline__ void mma16816(float* c, const u32* a, u32 b0, u32 b1) {
    asm volatile(
        "mma.sync.aligned.m16n8k16.row.col.f32.bf16.bf16.f32 "
        "{%0,%1,%2,%3}, {%4,%5,%6,%7}, {%8,%9}, {%0,%1,%2,%3};"
        : "+f"(c[0]), "+f"(c[1]), "+f"(c[2]), "+f"(c[3])
        : "r"(a[0]), "r"(a[1]), "r"(a[2]), "r"(a[3]), "r"(b0), "r"(b1));
}
__device__ __forceinline__ void ldsm4(u32 addr, u32* r) {
    asm volatile("ldmatrix.sync.aligned.m8n8.x4.shared.b16 {%0,%1,%2,%3}, [%4];"
        : "=r"(r[0]), "=r"(r[1]), "=r"(r[2]), "=r"(r[3]) : "r"(addr));
}
__device__ __forceinline__ void cp_async16(u32 dst, const void* src) {
    asm volatile("cp.async.cg.shared.global [%0], [%1], 16;" :: "r"(dst), "l"(src) : "memory");
}

// ---------------- kernel 1: transpose + bf16 convert dn -> g_dnT (padded) ----------------
__global__ __launch_bounds__(256) void k_cvt(const float* __restrict__ dn)
{
    if (blockIdx.x == 0 && blockIdx.y == 0 && threadIdx.x == 0) g_max_enc = 0u;
    __shared__ __nv_bfloat16 s[64][72];
    int p0 = blockIdx.x * 64, d0 = blockIdx.y * 64;
    int tid = threadIdx.x;
    #pragma unroll
    for (int i = 0; i < 16; i++) {
        int idx = tid + i * 256;
        int pl = idx >> 6, dl = idx & 63;
        int p  = p0 + pl;
        int sp_ = p / NPADS, ii = p % NPADS;
        float v = 0.0f;
        if (ii < NPER) {
            int node = sp_ * NPER + ii;
            v = dn[(size_t)node * DIM + d0 + dl];
        }
        s[pl][dl] = __float2bfloat16(v);
    }
    __syncthreads();
    #pragma unroll
    for (int i = 0; i < 16; i++) {
        int idx = tid + i * 256;
        int dl = idx >> 6, pl = idx & 63;
        g_dnT[d0 + dl][p0 + pl] = s[pl][dl];
    }
}

// ---------------- kernel 2: sp, sn dot products + max(sn) ----------------
__global__ __launch_bounds__(256) void k_scores(
    const float* __restrict__ pf, const float* __restrict__ dn,
    const float* __restrict__ ak)
{
    int tid  = threadIdx.x;
    int lane = tid & 31;
    int gw   = blockIdx.x * 8 + (tid >> 5);

    float v = 0.0f;
    bool isn = false;
    if (gw < B_PAT) {
        const float4* r = (const float4*)(pf + (size_t)gw * DIM);
        const float4* w = (const float4*)ak;
        #pragma unroll
        for (int k = 0; k < 2; k++) {
            float4 x  = r[lane * 2 + k];
            float4 ww = __ldg(&w[lane * 2 + k]);
            v += x.x * ww.x + x.y * ww.y + x.z * ww.z + x.w * ww.w;
        }
    } else if (gw < B_PAT + N_DIS) {
        isn = true;
        const float4* r = (const float4*)(dn + (size_t)(gw - B_PAT) * DIM);
        const float4* w = (const float4*)(ak + DIM);
        #pragma unroll
        for (int k = 0; k < 2; k++) {
            float4 x  = r[lane * 2 + k];
            float4 ww = __ldg(&w[lane * 2 + k]);
            v += x.x * ww.x + x.y * ww.y + x.z * ww.z + x.w * ww.w;
        }
    }
    #pragma unroll
    for (int o = 16; o; o >>= 1) v += __shfl_xor_sync(0xffffffffu, v, o);

    if (lane == 0) {
        if (gw < B_PAT)              g_sp[gw]         = v;
        else if (gw < B_PAT + N_DIS) g_sn[gw - B_PAT] = v;
    }

    __shared__ float wmax[8];
    float mv = isn ? v : -CUDART_INF_F;
    if (lane == 0) wmax[tid >> 5] = mv;
    __syncthreads();
    if (tid == 0) {
        float m = wmax[0];
        #pragma unroll
        for (int i = 1; i < 8; i++) m = fmaxf(m, wmax[i]);
        if (m > -CUDART_INF_F) atomicMax(&g_max_enc, enc_f(m));
    }
}

// ---------------- kernel 3: main fused GEMM, pipelined fragments ----------------
// grid (PT, NSK), 512 threads = 16 warps, warp tile 32x64.
__global__ __launch_bounds__(NTHR, 1) void k_main()
{
    extern __shared__ char smem[];
    char*  As_base = smem + OFF_A;
    float* sn_s    = (float*)(smem + OFF_SN);
    float* den_s   = (float*)(smem + OFF_DEN);
    const u32 sbA  = smem_u32(As_base);
    const u32 sbB  = sbA + OFF_B;

    const int tid  = threadIdx.x;
    const int wid  = tid >> 5;
    const int lane = tid & 31;
    const int wm   = wid & 3;
    const int wn   = wid >> 2;
    const int g    = lane >> 2;
    const int tig  = lane & 3;
    const int split = blockIdx.y;
    const int b0p   = blockIdx.x * BM;
    const int nbase = split * NPER;
    const int pbase = split * NPADS;

    const int arow = tid & 127;      // A-fill: patient row
    const int kq   = tid >> 7;       // A-fill: k-quarter 0..3 (16 k's each)

    const float sp    = g_sp[b0p + arow];
    const float maxsn = dec_f(g_max_enc);
    float mt = sp + maxsn;
    mt = fmaxf(mt, LEAKY * mt);
    const float mL2E = mt * L2EF;
    float den = 0.0f;

    for (int i = tid; i < NPER; i += NTHR) sn_s[i] = g_sn[nbase + i];

    // one half (gq) of this thread's A contribution for chunk c
    auto fillA_half = [&](int c, int gq) {
        char* ab = As_base + (c & 1) * A_BYTES;
        u32 pk[4];
        #pragma unroll
        for (int e = 0; e < 4; e++) {
            int kl   = kq * 16 + gq * 8 + e * 2;
            int kloc = c * KC + kl;
            float sn0 = (kloc     < NPER) ? sn_s[kloc]     : -CUDART_INF_F;
            float sn1 = (kloc + 1 < NPER) ? sn_s[kloc + 1] : -CUDART_INF_F;
            float t0 = sp + sn0, t1 = sp + sn1;
            t0 = fmaxf(t0, LEAKY * t0);
            t1 = fmaxf(t1, LEAKY * t1);
            float w0 = ex2(fmaf(t0, L2EF, -mL2E));
            float w1 = ex2(fmaf(t1, L2EF, -mL2E));
            den += w0 + w1;
            asm("cvt.rn.satfinite.bf16x2.f32 %0, %1, %2;" : "=r"(pk[e]) : "f"(w1), "f"(w0));
        }
        int k8 = kq * 2 + gq;
        *(uint4*)(ab + arow * 128 + ((k8 ^ (arow & 7)) << 4)) =
            make_uint4(pk[0], pk[1], pk[2], pk[3]);
    };
    auto fill_B = [&](int c) {                  // cp.async, 4 x 16B per thread
        u32 bb = sbB + (u32)((c & 1) * B_BYTES);
        int p0c = pbase + c * KC;
        #pragma unroll
        for (int it = 0; it < 4; it++) {
            int u  = tid + it * NTHR;           // 0..2047
            int d  = u >> 3;                    // dim row 0..255
            int k8 = u & 7;
            const void* src = (const char*)g_dnT + (size_t)d * (NPAD * 2)
                            + (size_t)(p0c + k8 * 8) * 2;
            cp_async16(bb + (u32)(d * 128 + ((k8 ^ (d & 7)) << 4)), src);
        }
        asm volatile("cp.async.commit_group;" ::: "memory");
    };

    // ldmatrix lane mapping
    const int a_r    = wm * 32 + (lane & 15);
    const int a_kh   = lane >> 4;
    const int b_jsel = lane >> 4;
    const int b_kh   = (lane >> 3) & 1;
    const int b_row  = lane & 7;

    float acc[2][8][4];
    #pragma unroll
    for (int i = 0; i < 2; i++)
        #pragma unroll
        for (int j = 0; j < 8; j++)
            #pragma unroll
            for (int q = 0; q < 4; q++) acc[i][j][q] = 0.0f;

    fill_B(0);
    __syncthreads();      // sn_s ready before fill_A
    fillA_half(0, 0);
    fillA_half(0, 1);
    asm volatile("cp.async.wait_group 0;" ::: "memory");
    __syncthreads();

    for (int c = 0; c < NCH; c++) {
        const bool more = (c + 1 < NCH);
        if (more) fill_B(c + 1);

        const u32 Aoff = sbA + (u32)((c & 1) * A_BYTES);
        const u32 Boff = sbB + (u32)((c & 1) * B_BYTES);

        // fragment pipeline: prefetch one LDSM group ahead
        u32 a_cur[2][4], b_cur[4];
        ldsm4(Aoff + swz8(a_r,      a_kh * 8), a_cur[0]);
        ldsm4(Aoff + swz8(a_r + 16, a_kh * 8), a_cur[1]);
        ldsm4(Boff + swz8(wn * 64 + b_jsel * 8 + b_row, b_kh * 8), b_cur);

        #pragma unroll
        for (int ks = 0; ks < 4; ks++) {
            #pragma unroll
            for (int jp = 0; jp < 4; jp++) {
                u32 b_nxt[4], a_nxt[2][4];
                if (jp < 3) {
                    ldsm4(Boff + swz8(wn * 64 + ((jp + 1) * 2 + b_jsel) * 8 + b_row,
                                      ks * 16 + b_kh * 8), b_nxt);
                } else if (ks < 3) {
                    ldsm4(Aoff + swz8(a_r,      (ks + 1) * 16 + a_kh * 8), a_nxt[0]);
                    ldsm4(Aoff + swz8(a_r + 16, (ks + 1) * 16 + a_kh * 8), a_nxt[1]);
                    ldsm4(Boff + swz8(wn * 64 + b_jsel * 8 + b_row,
                                      (ks + 1) * 16 + b_kh * 8), b_nxt);
                }
                #pragma unroll
                for (int i = 0; i < 2; i++) {
                    mma16816(acc[i][jp * 2],     a_cur[i], b_cur[0], b_cur[1]);
                    mma16816(acc[i][jp * 2 + 1], a_cur[i], b_cur[2], b_cur[3]);
                }
                if (jp < 3) {
                    #pragma unroll
                    for (int q = 0; q < 4; q++) b_cur[q] = b_nxt[q];
                } else if (ks < 3) {
                    #pragma unroll
                    for (int i = 0; i < 2; i++)
                        #pragma unroll
                        for (int q = 0; q < 4; q++) a_cur[i][q] = a_nxt[i][q];
                    #pragma unroll
                    for (int q = 0; q < 4; q++) b_cur[q] = b_nxt[q];
                }
            }
            // interleave next chunk's A computation into the MMA stream
            if (more && ks == 0) fillA_half(c + 1, 0);
            if (more && ks == 2) fillA_half(c + 1, 1);
        }

        if (more) asm volatile("cp.async.wait_group 0;" ::: "memory");
        __syncthreads();
    }

    // denominator reduce (fp32 exact): 4 k-quarter partials per row
    den_s[tid] = den;
    __syncthreads();
    if (tid < 128) {
        float s = den_s[tid] + den_s[tid + 128] + den_s[tid + 256] + den_s[tid + 384];
        g_den[split][b0p + tid] = s;
    }

    // epilogue: accumulators -> g_num
    #pragma unroll
    for (int i = 0; i < 2; i++) {
        int m = b0p + wm * 32 + i * 16 + g;
        #pragma unroll
        for (int j = 0; j < 8; j++) {
            int col = wn * 64 + j * 8 + tig * 2;
            *(float2*)&g_num[split][m][col]     = make_float2(acc[i][j][0], acc[i][j][1]);
            *(float2*)&g_num[split][m + 8][col] = make_float2(acc[i][j][2], acc[i][j][3]);
        }
    }
}

// ---------------- kernel 4: denominator reduce ----------------
__global__ void k_den()
{
    int b = blockIdx.x * blockDim.x + threadIdx.x;
    if (b < B_PAT) {
        float s = 0.0f;
        #pragma unroll
        for (int i = 0; i < NSK; i++) s += g_den[i][b];
        g_invden[b] = 1.0f / s;
    }
}

// ---------------- kernel 5: finalize out = pf + num * invden ----------------
__global__ void k_fin(const float* __restrict__ pf, float* __restrict__ out)
{
    int idx = blockIdx.x * blockDim.x + threadIdx.x;
    if (idx >= B_PAT * DIM / 4) return;
    int b = idx >> 6;
    float4 p = ((const float4*)pf)[idx];
    float4 s = make_float4(0.f, 0.f, 0.f, 0.f);
    const float4* num4 = (const float4*)g_num;
    #pragma unroll
    for (int i = 0; i < NSK; i++) {
        float4 v = num4[(size_t)i * (B_PAT * DIM / 4) + idx];
        s.x += v.x; s.y += v.y; s.z += v.z; s.w += v.w;
    }
    float inv = g_invden[b];
    float4 o;
    o.x = p.x + s.x * inv;  o.y = p.y + s.y * inv;
    o.z = p.z + s.z * inv;  o.w = p.w + s.w * inv;
    ((float4*)out)[idx] = o;
}

// ---------------- launch ----------------
extern "C" void kernel_launch(void* const* d_in, const int* in_sizes, int n_in,
                              void* d_out, int out_size)
{
    const float* pf = (const float*)d_in[0];
    const float* dn = (const float*)d_in[1];
    const float* ak = (const float*)d_in[2];
    float* out = (float*)d_out;

    static int configured = 0;
    if (!configured) {
        cudaFuncSetAttribute(k_main, cudaFuncAttributeMaxDynamicSharedMemorySize, SMEM_TOTAL);
        configured = 1;
    }

    k_cvt<<<dim3(NPAD / 64, DIM / 64), 256>>>(dn);
    k_scores<<<(B_PAT + N_DIS) / 8, 256>>>(pf, dn, ak);
    k_main<<<dim3(PT, NSK), NTHR, SMEM_TOTAL>>>();
    k_den<<<(B_PAT + 255) / 256, 256>>>();
    k_fin<<<(B_PAT * DIM / 4 + 255) / 256, 256>>>(pf, out);
}

// round 12
// speedup vs baseline: 1.5006x; 1.5006x over previous
#include <cuda_runtime.h>
#include <cuda_bf16.h>
#include <math_constants.h>
#include <cstdint>

#define B_PAT 4096
#define N_DIS 10000
#define DIM   256
#define BM    128                 // patients per CTA (GEMM M)
#define KC    64                  // nodes per chunk (GEMM K chunk)
#define NSK   4                   // K splits
#define NPER  (N_DIS/NSK)         // 2500 valid nodes per split
#define NCH   ((NPER+KC-1)/KC)    // 40 chunks per split
#define NPADS (NCH*KC)            // 2560 padded columns per split
#define NPAD  (NSK*NPADS)         // 10240
#define PT    (B_PAT/BM)          // 32
#define NTHR  512                 // 16 warps
#define LEAKY 0.2f
#define L2EF  1.4426950408889634f

// dynamic smem layout
#define A_BYTES  (BM*KC*2)                // 16384 per buffer
#define B_BYTES  (DIM*KC*2)               // 32768 per buffer
#define OFF_A    0
#define OFF_B    (2*A_BYTES)              // 32768
#define OFF_SN   (OFF_B + 2*B_BYTES)      // 98304
#define OFF_DEN  (OFF_SN + NPER*4)        // 108304
#define SMEM_TOTAL (OFF_DEN + NTHR*4)     // 110352

typedef uint32_t u32;

// ---------------- device globals (no allocation) ----------------
__device__ float        g_sp[B_PAT];
__device__ float        g_sn[N_DIS];
__device__ unsigned int g_max_enc;
// padded split-major transpose: split s owns padded cols [s*NPADS, (s+1)*NPADS)
__device__ __align__(16) __nv_bfloat16 g_dnT[DIM][NPAD];
__device__ float        g_num[NSK][B_PAT][DIM];
__device__ float        g_den[NSK][B_PAT];

// ---------------- helpers ----------------
__device__ __forceinline__ unsigned enc_f(float f) {
    unsigned u = __float_as_uint(f);
    return (u & 0x80000000u) ? ~u : (u | 0x80000000u);
}
__device__ __forceinline__ float dec_f(unsigned e) {
    return __uint_as_float((e & 0x80000000u) ? (e ^ 0x80000000u) : ~e);
}
__device__ __forceinline__ float ex2(float x) {
    float r; asm("ex2.approx.ftz.f32 %0, %1;" : "=f"(r) : "f"(x)); return r;
}
__device__ __forceinline__ u32 smem_u32(const void* p) {
    u32 a;
    asm("{ .reg .u64 t; cvta.to.shared.u64 t, %1; cvt.u32.u64 %0, t; }" : "=r"(a) : "l"(p));
    return a;
}
__device__ __forceinline__ void mma16816(float* c, const u32* a, u32 b0, u32 b1) {
    asm volatile(
        "mma.sync.aligned.m16n8k16.row.col.f32.bf16.bf16.f32 "
        "{%0,%1,%2,%3}, {%4,%5,%6,%7}, {%8,%9}, {%0,%1,%2,%3};"
        : "+f"(c[0]), "+f"(c[1]), "+f"(c[2]), "+f"(c[3])
        : "r"(a[0]), "r"(a[1]), "r"(a[2]), "r"(a[3]), "r"(b0), "r"(b1));
}
__device__ __forceinline__ void ldsm4(u32 addr, u32* r) {
    asm volatile("ldmatrix.sync.aligned.m8n8.x4.shared.b16 {%0,%1,%2,%3}, [%4];"
        : "=r"(r[0]), "=r"(r[1]), "=r"(r[2]), "=r"(r[3]) : "r"(addr));
}
__device__ __forceinline__ void cp_async16(u32 dst, const void* src) {
    asm volatile("cp.async.cg.shared.global [%0], [%1], 16;" :: "r"(dst), "l"(src) : "memory");
}

// ---------------- kernel 1: transpose + bf16 convert dn -> g_dnT (padded) ----------------
__global__ __launch_bounds__(256) void k_cvt(const float* __restrict__ dn)
{
    if (blockIdx.x == 0 && blockIdx.y == 0 && threadIdx.x == 0) g_max_enc = 0u;
    __shared__ __nv_bfloat16 s[64][72];
    int p0 = blockIdx.x * 64, d0 = blockIdx.y * 64;
    int tid = threadIdx.x;
    #pragma unroll
    for (int i = 0; i < 16; i++) {
        int idx = tid + i * 256;
        int pl = idx >> 6, dl = idx & 63;
        int p  = p0 + pl;
        int sp_ = p / NPADS, ii = p % NPADS;
        float v = 0.0f;
        if (ii < NPER) {
            int node = sp_ * NPER + ii;
            v = dn[(size_t)node * DIM + d0 + dl];
        }
        s[pl][dl] = __float2bfloat16(v);
    }
    __syncthreads();
    #pragma unroll
    for (int i = 0; i < 16; i++) {
        int idx = tid + i * 256;
        int dl = idx >> 6, pl = idx & 63;
        g_dnT[d0 + dl][p0 + pl] = s[pl][dl];
    }
}

// ---------------- kernel 2: sp, sn dot products + max(sn) ----------------
__global__ __launch_bounds__(256) void k_scores(
    const float* __restrict__ pf, const float* __restrict__ dn,
    const float* __restrict__ ak)
{
    int tid  = threadIdx.x;
    int lane = tid & 31;
    int gw   = blockIdx.x * 8 + (tid >> 5);

    float v = 0.0f;
    bool isn = false;
    if (gw < B_PAT) {
        const float4* r = (const float4*)(pf + (size_t)gw * DIM);
        const float4* w = (const float4*)ak;
        #pragma unroll
        for (int k = 0; k < 2; k++) {
            float4 x  = r[lane * 2 + k];
            float4 ww = __ldg(&w[lane * 2 + k]);
            v += x.x * ww.x + x.y * ww.y + x.z * ww.z + x.w * ww.w;
        }
    } else if (gw < B_PAT + N_DIS) {
        isn = true;
        const float4* r = (const float4*)(dn + (size_t)(gw - B_PAT) * DIM);
        const float4* w = (const float4*)(ak + DIM);
        #pragma unroll
        for (int k = 0; k < 2; k++) {
            float4 x  = r[lane * 2 + k];
            float4 ww = __ldg(&w[lane * 2 + k]);
            v += x.x * ww.x + x.y * ww.y + x.z * ww.z + x.w * ww.w;
        }
    }
    #pragma unroll
    for (int o = 16; o; o >>= 1) v += __shfl_xor_sync(0xffffffffu, v, o);

    if (lane == 0) {
        if (gw < B_PAT)              g_sp[gw]         = v;
        else if (gw < B_PAT + N_DIS) g_sn[gw - B_PAT] = v;
    }

    __shared__ float wmax[8];
    float mv = isn ? v : -CUDART_INF_F;
    if (lane == 0) wmax[tid >> 5] = mv;
    __syncthreads();
    if (tid == 0) {
        float m = wmax[0];
        #pragma unroll
        for (int i = 1; i < 8; i++) m = fmaxf(m, wmax[i]);
        if (m > -CUDART_INF_F) atomicMax(&g_max_enc, enc_f(m));
    }
}

// ---------------- kernel 3: main fused GEMM, grouped-LDSM inner loop ----------------
// grid (PT, NSK), 512 threads = 16 warps, warp tile 32x64: wm=wid&3, wn=wid>>2.
__global__ __launch_bounds__(NTHR, 1) void k_main()
{
    extern __shared__ char smem[];
    char*  As_base = smem + OFF_A;
    float* sn_s    = (float*)(smem + OFF_SN);
    float* den_s   = (float*)(smem + OFF_DEN);
    const u32 sbA  = smem_u32(As_base);
    const u32 sbB  = sbA + OFF_B;

    const int tid  = threadIdx.x;
    const int wid  = tid >> 5;
    const int lane = tid & 31;
    const int wm   = wid & 3;
    const int wn   = wid >> 2;
    const int g    = lane >> 2;
    const int tig  = lane & 3;
    const int split = blockIdx.y;
    const int b0p   = blockIdx.x * BM;
    const int nbase = split * NPER;
    const int pbase = split * NPADS;

    const int arow = tid & 127;      // A-fill: patient row
    const int kq   = tid >> 7;       // A-fill: k-quarter 0..3 (16 k's each)

    const float sp    = g_sp[b0p + arow];
    const float maxsn = dec_f(g_max_enc);
    float mt = sp + maxsn;
    mt = fmaxf(mt, LEAKY * mt);      // exact row max of leaky-relu scores
    const float mL2E = mt * L2EF;
    float den = 0.0f;

    for (int i = tid; i < NPER; i += NTHR) sn_s[i] = g_sn[nbase + i];

    auto fill_A = [&](int c) {
        char* ab = As_base + (c & 1) * A_BYTES;
        #pragma unroll
        for (int gq = 0; gq < 2; gq++) {
            u32 pk[4];
            #pragma unroll
            for (int e = 0; e < 4; e++) {
                int kl   = kq * 16 + gq * 8 + e * 2;
                int kloc = c * KC + kl;
                float sn0 = (kloc     < NPER) ? sn_s[kloc]     : -CUDART_INF_F;
                float sn1 = (kloc + 1 < NPER) ? sn_s[kloc + 1] : -CUDART_INF_F;
                float t0 = sp + sn0, t1 = sp + sn1;
                t0 = fmaxf(t0, LEAKY * t0);
                t1 = fmaxf(t1, LEAKY * t1);
                float w0 = ex2(fmaf(t0, L2EF, -mL2E));
                float w1 = ex2(fmaf(t1, L2EF, -mL2E));
                den += w0 + w1;
                asm("cvt.rn.satfinite.bf16x2.f32 %0, %1, %2;" : "=r"(pk[e]) : "f"(w1), "f"(w0));
            }
            int k8 = kq * 2 + gq;
            *(uint4*)(ab + arow * 128 + ((k8 ^ (arow & 7)) << 4)) =
                make_uint4(pk[0], pk[1], pk[2], pk[3]);
        }
    };
    auto fill_B = [&](int c) {                  // cp.async, 4 x 16B per thread
        u32 bb = sbB + (u32)((c & 1) * B_BYTES);
        int p0c = pbase + c * KC;
        #pragma unroll
        for (int it = 0; it < 4; it++) {
            int u  = tid + it * NTHR;           // 0..2047
            int d  = u >> 3;                    // dim row 0..255
            int k8 = u & 7;
            const void* src = (const char*)g_dnT + (size_t)d * (NPAD * 2)
                            + (size_t)(p0c + k8 * 8) * 2;
            cp_async16(bb + (u32)(d * 128 + ((k8 ^ (d & 7)) << 4)), src);
        }
        asm volatile("cp.async.commit_group;" ::: "memory");
    };

    // ldmatrix lane mapping
    const int a_r    = wm * 32 + (lane & 15);
    const int a_kh   = lane >> 4;
    const int b_jsel = lane >> 4;
    const int b_kh   = (lane >> 3) & 1;
    const int b_row  = lane & 7;

    float acc[2][8][4];
    #pragma unroll
    for (int i = 0; i < 2; i++)
        #pragma unroll
        for (int j = 0; j < 8; j++)
            #pragma unroll
            for (int q = 0; q < 4; q++) acc[i][j][q] = 0.0f;

    fill_B(0);
    __syncthreads();      // sn_s ready before fill_A
    fill_A(0);
    asm volatile("cp.async.wait_group 0;" ::: "memory");
    __syncthreads();

    for (int c = 0; c < NCH; c++) {
        if (c + 1 < NCH) { fill_B(c + 1); fill_A(c + 1); }

        const u32 Aoff = sbA + (u32)((c & 1) * A_BYTES);
        const u32 Boff = sbB + (u32)((c & 1) * B_BYTES);
        #pragma unroll
        for (int ks = 0; ks < 4; ks++) {
            // load ALL fragments for this ks first (6 back-to-back LDSM),
            // then issue the 32 MMAs — only the first MMA eats smem latency.
            u32 a[2][4], b[4][4];
            #pragma unroll
            for (int i = 0; i < 2; i++) {
                int r = a_r + i * 16;
                int k = ks * 16 + a_kh * 8;
                ldsm4(Aoff + (u32)(r * 128 + ((((k >> 3) ^ (r & 7))) << 4)), a[i]);
            }
            #pragma unroll
            for (int jp = 0; jp < 4; jp++) {
                int r = wn * 64 + (jp * 2 + b_jsel) * 8 + b_row;
                int k = ks * 16 + b_kh * 8;
                ldsm4(Boff + (u32)(r * 128 + ((((k >> 3) ^ (r & 7))) << 4)), b[jp]);
            }
            #pragma unroll
            for (int jp = 0; jp < 4; jp++)
                #pragma unroll
                for (int i = 0; i < 2; i++) {
                    mma16816(acc[i][jp * 2],     a[i], b[jp][0], b[jp][1]);
                    mma16816(acc[i][jp * 2 + 1], a[i], b[jp][2], b[jp][3]);
                }
        }
        if (c + 1 < NCH) asm volatile("cp.async.wait_group 0;" ::: "memory");
        __syncthreads();
    }

    // denominator reduce (fp32 exact): 4 k-quarter partials per row
    den_s[tid] = den;
    __syncthreads();
    if (tid < 128) {
        float s = den_s[tid] + den_s[tid + 128] + den_s[tid + 256] + den_s[tid + 384];
        g_den[split][b0p + tid] = s;
    }

    // epilogue: accumulators -> g_num
    #pragma unroll
    for (int i = 0; i < 2; i++) {
        int m = b0p + wm * 32 + i * 16 + g;
        #pragma unroll
        for (int j = 0; j < 8; j++) {
            int col = wn * 64 + j * 8 + tig * 2;
            *(float2*)&g_num[split][m][col]     = make_float2(acc[i][j][0], acc[i][j][1]);
            *(float2*)&g_num[split][m + 8][col] = make_float2(acc[i][j][2], acc[i][j][3]);
        }
    }
}

// ---------------- kernel 4: finalize out = pf + num/den (den fold-in) ----------------
__global__ void k_fin(const float* __restrict__ pf, float* __restrict__ out)
{
    int idx = blockIdx.x * blockDim.x + threadIdx.x;   // float4 index
    if (idx >= B_PAT * DIM / 4) return;
    int b = idx >> 6;
    float4 p = ((const float4*)pf)[idx];
    float4 s = make_float4(0.f, 0.f, 0.f, 0.f);
    const float4* num4 = (const float4*)g_num;
    #pragma unroll
    for (int i = 0; i < NSK; i++) {
        float4 v = num4[(size_t)i * (B_PAT * DIM / 4) + idx];
        s.x += v.x; s.y += v.y; s.z += v.z; s.w += v.w;
    }
    float den = g_den[0][b] + g_den[1][b] + g_den[2][b] + g_den[3][b];
    float inv = 1.0f / den;
    float4 o;
    o.x = p.x + s.x * inv;  o.y = p.y + s.y * inv;
    o.z = p.z + s.z * inv;  o.w = p.w + s.w * inv;
    ((float4*)out)[idx] = o;
}

// ---------------- launch ----------------
extern "C" void kernel_launch(void* const* d_in, const int* in_sizes, int n_in,
                              void* d_out, int out_size)
{
    const float* pf = (const float*)d_in[0];
    const float* dn = (const float*)d_in[1];
    const float* ak = (const float*)d_in[2];
    float* out = (float*)d_out;

    static int configured = 0;
    if (!configured) {
        cudaFuncSetAttribute(k_main, cudaFuncAttributeMaxDynamicSharedMemorySize, SMEM_TOTAL);
        configured = 1;
    }

    k_cvt<<<dim3(NPAD / 64, DIM / 64), 256>>>(dn);
    k_scores<<<(B_PAT + N_DIS) / 8, 256>>>(pf, dn, ak);
    k_main<<<dim3(PT, NSK), NTHR, SMEM_TOTAL>>>();
    k_fin<<<(B_PAT * DIM / 4 + 255) / 256, 256>>>(pf, out);
}